// round 2
// baseline (speedup 1.0000x reference)
#include <cuda_runtime.h>
#include <cuda_bf16.h>
#include <cstdint>

#define S_LEN 2048
#define B_N   64
#define W5    50
#define E_N   128
#define H_N   256
#define G_N   1024
#define NCTA  128

// ---------------- static device scratch (allocation-free) ----------------
__device__ float g_emb[(size_t)S_LEN * B_N * E_N];      // [s][b][e]  64 MB
__device__ float g_xg [(size_t)S_LEN * G_N * B_N];      // [s][g][b] 512 MB
__device__ float g_hs [(size_t)S_LEN * B_N * H_N];      // [s][b][j] 128 MB (h after step s)
__device__ unsigned g_arrive_arr[32];
__device__ unsigned g_release_arr[32];

__device__ __forceinline__ float sigf(float x) { return 1.0f / (1.0f + __expf(-x)); }

// =============== Phase 1a: emb = relu(pw @ Wemb^T + bemb) ===============
// grid = S_LEN, 256 threads
__global__ void __launch_bounds__(256) emb_kernel(const float* __restrict__ pw,
                                                  const float* __restrict__ Wemb,
                                                  const float* __restrict__ bemb) {
    __shared__ float pw_s[64 * 51];
    __shared__ float we_s[128 * 51];
    const int s = blockIdx.x;
    const int t = threadIdx.x;

    for (int i = t; i < 64 * 50; i += 256) {
        int b = i / 50, k = i - b * 50;
        pw_s[b * 51 + k] = pw[((size_t)b * S_LEN + s) * W5 + k];
    }
    for (int i = t; i < 128 * 50; i += 256) {
        int e = i / 50, k = i - e * 50;
        we_s[e * 51 + k] = Wemb[e * 50 + k];
    }
    __syncthreads();

    const int e = t & 127, bh = t >> 7;
    float wreg[50];
#pragma unroll
    for (int k = 0; k < 50; k++) wreg[k] = we_s[e * 51 + k];
    const float be = bemb[e];
    float* outp = g_emb + (size_t)s * (B_N * E_N);
    for (int bb = 0; bb < 32; bb++) {
        int b = bh * 32 + bb;
        float acc = be;
#pragma unroll
        for (int k = 0; k < 50; k++) acc = fmaf(pw_s[b * 51 + k], wreg[k], acc);
        outp[b * 128 + e] = fmaxf(acc, 0.0f);
    }
}

// =============== Phase 1b: x_gates[s][g][b] = Wih @ emb^T + (bih+bhh) ===============
// grid = (16 gtiles, S_LEN), 256 threads, dynamic smem 2*128*68*4
__global__ void __launch_bounds__(256) xgates_kernel(const float* __restrict__ Wih,
                                                     const float* __restrict__ bih,
                                                     const float* __restrict__ bhh) {
    extern __shared__ float sm[];
    float* wT = sm;               // [e=128][g=64] pitch 68
    float* eT = sm + 128 * 68;    // [e=128][b=64] pitch 68
    const int s = blockIdx.y, gt = blockIdx.x;
    const int t = threadIdx.x;

    for (int i = t; i < 64 * 128; i += 256) {
        int g = i >> 7, e = i & 127;
        wT[e * 68 + g] = Wih[((size_t)(gt * 64 + g)) * 128 + e];
    }
    const float* embp = g_emb + (size_t)s * (B_N * E_N);
    for (int i = t; i < 64 * 128; i += 256) {
        int b = i >> 7, e = i & 127;
        eT[e * 68 + b] = embp[b * 128 + e];
    }
    __syncthreads();

    const int gq = t & 15, bq = t >> 4;
    float acc[4][4];
#pragma unroll
    for (int i = 0; i < 4; i++)
#pragma unroll
        for (int j = 0; j < 4; j++) acc[i][j] = 0.0f;

#pragma unroll 4
    for (int e = 0; e < 128; e++) {
        float4 wa = *(float4*)&wT[e * 68 + gq * 4];
        float4 eb = *(float4*)&eT[e * 68 + bq * 4];
        float w[4] = {wa.x, wa.y, wa.z, wa.w};
        float x[4] = {eb.x, eb.y, eb.z, eb.w};
#pragma unroll
        for (int i = 0; i < 4; i++)
#pragma unroll
            for (int j = 0; j < 4; j++) acc[i][j] = fmaf(w[i], x[j], acc[i][j]);
    }

    float* xgp = g_xg + (size_t)s * G_N * B_N;
#pragma unroll
    for (int i = 0; i < 4; i++) {
        int gg = gt * 64 + gq * 4 + i;
        float bs = bih[gg] + bhh[gg];
        float4 o = make_float4(acc[i][0] + bs, acc[i][1] + bs, acc[i][2] + bs, acc[i][3] + bs);
        *(float4*)&xgp[(size_t)gg * 64 + bq * 4] = o;
    }
}

// =============== Phase 2: persistent LSTM scan ===============
// grid = 128 CTAs x 128 threads. CTA ct owns h-cols j0=2*ct, j0+1.
// row index r = type*2 + jl  (type: 0=i,1=f,2=g,3=o ; jl in {0,1})
#define PH 260
__global__ void __launch_bounds__(128, 1) lstm_kernel(const float* __restrict__ Whh,
                                                      const float* __restrict__ h0,
                                                      const float* __restrict__ c0) {
    extern __shared__ float sm[];
    float* h_s    = sm;                 // [64][PH]
    float* w_s    = h_s + 64 * PH;      // [8][256]
    float* gate_s = w_s + 8 * 256;      // [8][64]

    const int t  = threadIdx.x;
    const int ct = blockIdx.x;
    const int j0 = ct * 2;

    // load W_hh rows for this CTA (persistent in smem)
    for (int i = t; i < 8 * 256; i += 128) {
        int r = i >> 8, k = i & 255;
        int tp = r >> 1, jl = r & 1;
        w_s[i] = Whh[((size_t)(tp * 256 + j0 + jl)) * 256 + k];
    }

    // c-state: thread t owns (jl_c = t>>6, b_c = t&63)
    const int jl_c = t >> 6, b_c = t & 63;
    float c = c0[b_c * 256 + j0 + jl_c];

    const int rp = t >> 5;       // 0..3 -> rows rp and rp+4
    const int b0 = t & 31;       // batches b0, b0+32
    const int g_r0 = ((rp >> 1)      * 256) + j0 + (rp & 1);
    const int g_r1 = (((rp >> 1) + 2) * 256) + j0 + (rp & 1);

    unsigned* arr = g_arrive_arr;
    volatile unsigned* rel = g_release_arr;

    __syncthreads();

    for (int s = 0; s < S_LEN; s++) {
        // stage h(s-1) into smem
        const float* hprev = (s == 0) ? h0 : (g_hs + (size_t)(s - 1) * (B_N * H_N));
        for (int i = t * 4; i < B_N * H_N; i += 128 * 4) {
            int b = i >> 8, k = i & 255;
            *(float4*)&h_s[b * PH + k] = *(const float4*)&hprev[i];
        }
        __syncthreads();

        const float* xgp = g_xg + (size_t)s * G_N * B_N;
        float a00 = xgp[(size_t)g_r0 * 64 + b0];
        float a01 = xgp[(size_t)g_r0 * 64 + b0 + 32];
        float a10 = xgp[(size_t)g_r1 * 64 + b0];
        float a11 = xgp[(size_t)g_r1 * 64 + b0 + 32];

        const float* w0  = &w_s[rp * 256];
        const float* w1  = &w_s[(rp + 4) * 256];
        const float* hb0 = &h_s[b0 * PH];
        const float* hb1 = &h_s[(b0 + 32) * PH];

#pragma unroll 8
        for (int k = 0; k < 256; k += 4) {
            float4 x0 = *(float4*)&hb0[k];
            float4 x1 = *(float4*)&hb1[k];
            float4 v0 = *(float4*)&w0[k];
            float4 v1 = *(float4*)&w1[k];
            a00 = fmaf(x0.x, v0.x, a00); a00 = fmaf(x0.y, v0.y, a00);
            a00 = fmaf(x0.z, v0.z, a00); a00 = fmaf(x0.w, v0.w, a00);
            a01 = fmaf(x1.x, v0.x, a01); a01 = fmaf(x1.y, v0.y, a01);
            a01 = fmaf(x1.z, v0.z, a01); a01 = fmaf(x1.w, v0.w, a01);
            a10 = fmaf(x0.x, v1.x, a10); a10 = fmaf(x0.y, v1.y, a10);
            a10 = fmaf(x0.z, v1.z, a10); a10 = fmaf(x0.w, v1.w, a10);
            a11 = fmaf(x1.x, v1.x, a11); a11 = fmaf(x1.y, v1.y, a11);
            a11 = fmaf(x1.z, v1.z, a11); a11 = fmaf(x1.w, v1.w, a11);
        }
        gate_s[rp * 64 + b0]            = a00;
        gate_s[rp * 64 + b0 + 32]       = a01;
        gate_s[(rp + 4) * 64 + b0]      = a10;
        gate_s[(rp + 4) * 64 + b0 + 32] = a11;
        __syncthreads();

        // combine gates, update state, write h
        {
            float iv = sigf(gate_s[(0 + jl_c) * 64 + b_c]);
            float fv = sigf(gate_s[(2 + jl_c) * 64 + b_c]);
            float gv = tanhf(gate_s[(4 + jl_c) * 64 + b_c]);
            float ov = sigf(gate_s[(6 + jl_c) * 64 + b_c]);
            c = fv * c + iv * gv;
            float h = ov * tanhf(c);
            g_hs[(size_t)s * (B_N * H_N) + b_c * 256 + j0 + jl_c] = h;
        }

        // grid barrier (monotonic, counters reset by host memset each launch)
        __threadfence();
        __syncthreads();
        if (t == 0) {
            unsigned prev = atomicAdd(&arr[0], 1u);
            if (prev == (unsigned)(NCTA * (s + 1) - 1)) {
                asm volatile("st.release.gpu.u32 [%0], %1;" :: "l"(&g_release_arr[0]),
                             "r"((unsigned)(s + 1)) : "memory");
            }
            unsigned v;
            do {
                asm volatile("ld.acquire.gpu.u32 %0, [%1];" : "=r"(v)
                             : "l"(&g_release_arr[0]) : "memory");
            } while (v < (unsigned)(s + 1));
        }
        __syncthreads();
        (void)rel;
    }
}

// =============== Phase 3: readout y = sigmoid(hs @ Wout^T + bout) ===============
// one warp per (s,b); 256 threads/block -> 8 pairs/block; 16384 blocks
__global__ void __launch_bounds__(256) readout_kernel(const float* __restrict__ Wout,
                                                      const float* __restrict__ bout,
                                                      float* __restrict__ y) {
    int pair = blockIdx.x * 8 + (threadIdx.x >> 5);
    int lane = threadIdx.x & 31;
    int s = pair >> 6, b = pair & 63;
    const float* h = g_hs + (size_t)s * (B_N * H_N) + b * 256;
    float4 a0 = *(const float4*)&h[lane * 4];
    float4 a1 = *(const float4*)&h[128 + lane * 4];
    float4 w0 = *(const float4*)&Wout[lane * 4];
    float4 w1 = *(const float4*)&Wout[128 + lane * 4];
    float acc = a0.x * w0.x + a0.y * w0.y + a0.z * w0.z + a0.w * w0.w
              + a1.x * w1.x + a1.y * w1.y + a1.z * w1.z + a1.w * w1.w;
#pragma unroll
    for (int off = 16; off > 0; off >>= 1) acc += __shfl_xor_sync(0xFFFFFFFFu, acc, off);
    if (lane == 0) y[pair] = sigf(acc + bout[0]);
}

// =============== host launcher ===============
extern "C" void kernel_launch(void* const* d_in, const int* in_sizes, int n_in,
                              void* d_out, int out_size) {
    const float* pw   = (const float*)d_in[0];
    const float* Wemb = (const float*)d_in[1];
    const float* bemb = (const float*)d_in[2];
    const float* Wih  = (const float*)d_in[3];
    const float* Whh  = (const float*)d_in[4];
    const float* bih  = (const float*)d_in[5];
    const float* bhh  = (const float*)d_in[6];
    const float* Wout = (const float*)d_in[7];
    const float* bout = (const float*)d_in[8];
    const float* h0   = (const float*)d_in[9];
    const float* c0   = (const float*)d_in[10];
    float* y = (float*)d_out;

    static bool attrs_set = false;
    const int xg_smem   = 2 * 128 * 68 * (int)sizeof(float);
    const int lstm_smem = (64 * PH + 8 * 256 + 8 * 64) * (int)sizeof(float);
    if (!attrs_set) {
        cudaFuncSetAttribute(xgates_kernel, cudaFuncAttributeMaxDynamicSharedMemorySize, xg_smem);
        cudaFuncSetAttribute(lstm_kernel,  cudaFuncAttributeMaxDynamicSharedMemorySize, lstm_smem);
        attrs_set = true;
    }

    void* p_arr = nullptr; void* p_rel = nullptr;
    cudaGetSymbolAddress(&p_arr, g_arrive_arr);
    cudaGetSymbolAddress(&p_rel, g_release_arr);
    cudaMemsetAsync(p_arr, 0, 32 * sizeof(unsigned));
    cudaMemsetAsync(p_rel, 0, 32 * sizeof(unsigned));

    emb_kernel<<<S_LEN, 256>>>(pw, Wemb, bemb);
    xgates_kernel<<<dim3(16, S_LEN), 256, xg_smem>>>(Wih, bih, bhh);
    lstm_kernel<<<NCTA, 128, lstm_smem>>>(Whh, h0, c0);
    readout_kernel<<<(S_LEN * B_N) / 8, 256>>>(Wout, bout, y);
}

// round 3
// speedup vs baseline: 1.4637x; 1.4637x over previous
#include <cuda_runtime.h>
#include <cuda_bf16.h>
#include <cstdint>

#define S_LEN 2048
#define B_N   64
#define W5    50
#define E_N   128
#define H_N   256
#define G_N   1024
#define NCTA  128

// ---------------- static device scratch (allocation-free) ----------------
__device__ float g_emb[(size_t)S_LEN * B_N * E_N];      // [s][b][e]
__device__ float g_xg [(size_t)S_LEN * G_N * B_N];      // [s][g][b]
__device__ float g_hs [(size_t)S_LEN * H_N * B_N];      // [s][j][b]  (h after step s)
__device__ unsigned g_arrive_arr[32];
__device__ unsigned g_release_arr[32];

__device__ __forceinline__ float sigf(float x) { return 1.0f / (1.0f + __expf(-x)); }

// =============== Phase 1a: emb = relu(pw @ Wemb^T + bemb) ===============
__global__ void __launch_bounds__(256) emb_kernel(const float* __restrict__ pw,
                                                  const float* __restrict__ Wemb,
                                                  const float* __restrict__ bemb) {
    __shared__ float pw_s[64 * 51];
    __shared__ float we_s[128 * 51];
    const int s = blockIdx.x;
    const int t = threadIdx.x;

    for (int i = t; i < 64 * 50; i += 256) {
        int b = i / 50, k = i - b * 50;
        pw_s[b * 51 + k] = pw[((size_t)b * S_LEN + s) * W5 + k];
    }
    for (int i = t; i < 128 * 50; i += 256) {
        int e = i / 50, k = i - e * 50;
        we_s[e * 51 + k] = Wemb[e * 50 + k];
    }
    __syncthreads();

    const int e = t & 127, bh = t >> 7;
    float wreg[50];
#pragma unroll
    for (int k = 0; k < 50; k++) wreg[k] = we_s[e * 51 + k];
    const float be = bemb[e];
    float* outp = g_emb + (size_t)s * (B_N * E_N);
    for (int bb = 0; bb < 32; bb++) {
        int b = bh * 32 + bb;
        float acc = be;
#pragma unroll
        for (int k = 0; k < 50; k++) acc = fmaf(pw_s[b * 51 + k], wreg[k], acc);
        outp[b * 128 + e] = fmaxf(acc, 0.0f);
    }
}

// =============== Phase 1b: x_gates[s][g][b] = Wih @ emb^T + (bih+bhh) ===============
// grid = (16 gtiles, S_LEN), 128 threads; 8g x 4b register tile per thread
#define XP 68
__global__ void __launch_bounds__(128) xgates_kernel(const float* __restrict__ Wih,
                                                     const float* __restrict__ bih,
                                                     const float* __restrict__ bhh) {
    extern __shared__ float sm[];
    float* wT = sm;               // [e=128][g=64] pitch XP
    float* eT = sm + 128 * XP;    // [e=128][b=64] pitch XP
    const int s = blockIdx.y, gt = blockIdx.x;
    const int t = threadIdx.x;

    // stage W tile: read [g][e] coalesced (e fast), store transposed
    for (int i = t; i < 64 * 128; i += 128) {
        int e = i & 127, g = i >> 7;
        wT[e * XP + g] = Wih[((size_t)(gt * 64 + g)) * 128 + e];
    }
    const float* embp = g_emb + (size_t)s * (B_N * E_N);
    for (int i = t; i < 64 * 128; i += 128) {
        int e = i & 127, b = i >> 7;
        eT[e * XP + b] = embp[b * 128 + e];
    }
    __syncthreads();

    const int gq = t >> 4;   // 0..7 -> 8 g's (broadcast w-loads across 16 lanes)
    const int bq = t & 15;   // 0..15 -> 4 b's
    float acc[8][4];
#pragma unroll
    for (int i = 0; i < 8; i++)
#pragma unroll
        for (int j = 0; j < 4; j++) acc[i][j] = 0.0f;

#pragma unroll 4
    for (int e = 0; e < 128; e++) {
        float4 w0 = *(float4*)&wT[e * XP + gq * 8];
        float4 w1 = *(float4*)&wT[e * XP + gq * 8 + 4];
        float4 hv = *(float4*)&eT[e * XP + bq * 4];
        float w[8] = {w0.x, w0.y, w0.z, w0.w, w1.x, w1.y, w1.z, w1.w};
        float x[4] = {hv.x, hv.y, hv.z, hv.w};
#pragma unroll
        for (int i = 0; i < 8; i++)
#pragma unroll
            for (int j = 0; j < 4; j++) acc[i][j] = fmaf(w[i], x[j], acc[i][j]);
    }

    float* xgp = g_xg + (size_t)s * G_N * B_N;
#pragma unroll
    for (int i = 0; i < 8; i++) {
        int gg = gt * 64 + gq * 8 + i;
        float bs = bih[gg] + bhh[gg];
        float4 o = make_float4(acc[i][0] + bs, acc[i][1] + bs, acc[i][2] + bs, acc[i][3] + bs);
        *(float4*)&xgp[(size_t)gg * 64 + bq * 4] = o;
    }
}

// =============== Phase 2: persistent LSTM scan ===============
// 128 CTAs x 256 threads. CTA ct owns h-cols j0=2*ct, j0+1 -> 8 gate rows
// r = tp*2 + jl  (tp: 0=i,1=f,2=g,3=o ; jl in {0,1}), Whh row = tp*256 + j0 + jl
#define HP 68      // h_s pitch (floats): k-major [256][64] padded
#define WP 12      // wT_s pitch: [k=256][r=8] padded
#define PP 10      // partials pitch: [r*64+b][kq=8] padded
__global__ void __launch_bounds__(256, 1) lstm_kernel(const float* __restrict__ Whh,
                                                      const float* __restrict__ h0,
                                                      const float* __restrict__ c0,
                                                      const float* __restrict__ xg) {
    extern __shared__ float sm[];
    float* h_s  = sm;                    // [256][HP]
    float* wT_s = h_s + 256 * HP;        // [256][WP]
    float* part = wT_s + 256 * WP;       // [512][PP]

    const int t  = threadIdx.x;
    const int ct = blockIdx.x;
    const int j0 = ct * 2;

    // load W_hh slice transposed: wT_s[k][r]
    for (int i = t; i < 8 * 256; i += 256) {
        int k = i & 255, r = i >> 8;
        int tp = r >> 1, jl = r & 1;
        wT_s[k * WP + r] = Whh[((size_t)(tp * 256 + j0 + jl)) * 256 + k];
    }

    // matvec thread mapping
    const int kq = t & 7;           // 8-way k-split, interleaved: k = kq + 8*kk
    const int bq = (t >> 3) & 15;   // 4 batches: 4*bq..+3
    const int rq = t >> 7;          // 4 rows:    4*rq..+3

    // gate/update thread mapping (t < 128)
    const int jl_c = t >> 6, b_c = t & 63;
    float c = 0.0f;
    if (t < 128) c = c0[b_c * 256 + j0 + jl_c];

    __syncthreads();

    for (int s = 0; s < S_LEN; s++) {
        // prefetch x-gates for this step (latency hidden under restage+matvec)
        float xr0 = 0.f, xr1 = 0.f, xr2 = 0.f, xr3 = 0.f;
        if (t < 128) {
            const float* xgp = xg + (size_t)s * (G_N * B_N);
            xr0 = __ldg(&xgp[(size_t)(0 * 256 + j0 + jl_c) * 64 + b_c]);
            xr1 = __ldg(&xgp[(size_t)(1 * 256 + j0 + jl_c) * 64 + b_c]);
            xr2 = __ldg(&xgp[(size_t)(2 * 256 + j0 + jl_c) * 64 + b_c]);
            xr3 = __ldg(&xgp[(size_t)(3 * 256 + j0 + jl_c) * 64 + b_c]);
        }

        // stage h(s-1) into smem, k-major
        if (s == 0) {
            for (int i = t; i < B_N * H_N; i += 256) {
                int b = i >> 8, k = i & 255;
                h_s[k * HP + b] = h0[i];           // h0 is [b][j]
            }
        } else {
            const float4* src = (const float4*)(g_hs + (size_t)(s - 1) * (H_N * B_N));
            for (int i = t; i < (H_N * B_N) / 4; i += 256) {
                int k = i >> 4, c4 = i & 15;
                *(float4*)&h_s[k * HP + c4 * 4] = src[i];   // [j][b] -> direct copy
            }
        }
        __syncthreads();

        // matvec: acc[i][j] = sum_k wT[k][4rq+i] * h[k][4bq+j]  over k = kq+8*kk
        float a00=0,a01=0,a02=0,a03=0, a10=0,a11=0,a12=0,a13=0;
        float a20=0,a21=0,a22=0,a23=0, a30=0,a31=0,a32=0,a33=0;
#pragma unroll 8
        for (int kk = 0; kk < 32; kk++) {
            int k = kq + (kk << 3);
            float4 hv = *(float4*)&h_s[k * HP + bq * 4];
            float4 wv = *(float4*)&wT_s[k * WP + rq * 4];
            a00 = fmaf(wv.x, hv.x, a00); a01 = fmaf(wv.x, hv.y, a01);
            a02 = fmaf(wv.x, hv.z, a02); a03 = fmaf(wv.x, hv.w, a03);
            a10 = fmaf(wv.y, hv.x, a10); a11 = fmaf(wv.y, hv.y, a11);
            a12 = fmaf(wv.y, hv.z, a12); a13 = fmaf(wv.y, hv.w, a13);
            a20 = fmaf(wv.z, hv.x, a20); a21 = fmaf(wv.z, hv.y, a21);
            a22 = fmaf(wv.z, hv.z, a22); a23 = fmaf(wv.z, hv.w, a23);
            a30 = fmaf(wv.w, hv.x, a30); a31 = fmaf(wv.w, hv.y, a31);
            a32 = fmaf(wv.w, hv.z, a32); a33 = fmaf(wv.w, hv.w, a33);
        }
        {
            float accv[4][4] = {{a00,a01,a02,a03},{a10,a11,a12,a13},
                                {a20,a21,a22,a23},{a30,a31,a32,a33}};
#pragma unroll
            for (int i = 0; i < 4; i++)
#pragma unroll
                for (int j = 0; j < 4; j++)
                    part[((4*rq + i) * 64 + 4*bq + j) * PP + kq] = accv[i][j];
        }
        __syncthreads();

        // reduce across kq, apply gates, update state, write h (coalesced [j][b])
        if (t < 128) {
            float gsum[4];
#pragma unroll
            for (int tp = 0; tp < 4; tp++) {
                int r = 2 * tp + jl_c;
                const float* pp = &part[(r * 64 + b_c) * PP];
                float ssum = pp[0] + pp[1] + pp[2] + pp[3] + pp[4] + pp[5] + pp[6] + pp[7];
                gsum[tp] = ssum;
            }
            float iv = sigf(gsum[0] + xr0);
            float fv = sigf(gsum[1] + xr1);
            float gv = tanhf(gsum[2] + xr2);
            float ov = sigf(gsum[3] + xr3);
            c = fv * c + iv * gv;
            float h = ov * tanhf(c);
            g_hs[(size_t)s * (H_N * B_N) + (j0 + jl_c) * 64 + b_c] = h;
        }

        // grid barrier (monotonic; counters zeroed by host memset each launch)
        __threadfence();
        __syncthreads();
        if (t == 0) {
            unsigned prev = atomicAdd(&g_arrive_arr[0], 1u);
            if (prev == (unsigned)(NCTA * (s + 1) - 1)) {
                asm volatile("st.release.gpu.u32 [%0], %1;" :: "l"(&g_release_arr[0]),
                             "r"((unsigned)(s + 1)) : "memory");
            }
            unsigned v;
            do {
                asm volatile("ld.acquire.gpu.u32 %0, [%1];" : "=r"(v)
                             : "l"(&g_release_arr[0]) : "memory");
            } while (v < (unsigned)(s + 1));
        }
        __syncthreads();
    }
}

// dummy kernel so ncu -s 5 -c 1 lands on lstm_kernel
__global__ void dummy_kernel() {}

// =============== Phase 3: readout y = sigmoid(Wout . h + bout), hs is [s][j][b] ===============
__global__ void __launch_bounds__(256) readout_kernel(const float* __restrict__ Wout,
                                                      const float* __restrict__ bout,
                                                      float* __restrict__ y) {
    __shared__ float4 part4[16][16];    // [jq][bq]
    const int s = blockIdx.x;
    const int t = threadIdx.x;
    const int bq = t & 15, jq = t >> 4;
    const float* hp = g_hs + (size_t)s * (H_N * B_N);
    float4 acc = make_float4(0.f, 0.f, 0.f, 0.f);
#pragma unroll
    for (int jj = 0; jj < 16; jj++) {
        int j = jq * 16 + jj;
        float4 hv = *(const float4*)&hp[j * 64 + bq * 4];
        float w = Wout[j];
        acc.x = fmaf(w, hv.x, acc.x); acc.y = fmaf(w, hv.y, acc.y);
        acc.z = fmaf(w, hv.z, acc.z); acc.w = fmaf(w, hv.w, acc.w);
    }
    part4[jq][bq] = acc;
    __syncthreads();
    if (t < 16) {
        float4 ssum = make_float4(0.f, 0.f, 0.f, 0.f);
#pragma unroll
        for (int q = 0; q < 16; q++) {
            float4 v = part4[q][t];
            ssum.x += v.x; ssum.y += v.y; ssum.z += v.z; ssum.w += v.w;
        }
        float bo = bout[0];
        float4 o = make_float4(sigf(ssum.x + bo), sigf(ssum.y + bo),
                               sigf(ssum.z + bo), sigf(ssum.w + bo));
        *(float4*)&y[s * 64 + t * 4] = o;
    }
}

// =============== host launcher ===============
extern "C" void kernel_launch(void* const* d_in, const int* in_sizes, int n_in,
                              void* d_out, int out_size) {
    const float* pw   = (const float*)d_in[0];
    const float* Wemb = (const float*)d_in[1];
    const float* bemb = (const float*)d_in[2];
    const float* Wih  = (const float*)d_in[3];
    const float* Whh  = (const float*)d_in[4];
    const float* bih  = (const float*)d_in[5];
    const float* bhh  = (const float*)d_in[6];
    const float* Wout = (const float*)d_in[7];
    const float* bout = (const float*)d_in[8];
    const float* h0   = (const float*)d_in[9];
    const float* c0   = (const float*)d_in[10];
    float* y = (float*)d_out;

    static bool attrs_set = false;
    const int xg_smem   = 2 * 128 * XP * (int)sizeof(float);
    const int lstm_smem = (256 * HP + 256 * WP + 512 * PP) * (int)sizeof(float);
    if (!attrs_set) {
        cudaFuncSetAttribute(xgates_kernel, cudaFuncAttributeMaxDynamicSharedMemorySize, xg_smem);
        cudaFuncSetAttribute(lstm_kernel,  cudaFuncAttributeMaxDynamicSharedMemorySize, lstm_smem);
        attrs_set = true;
    }

    void* p_arr = nullptr; void* p_rel = nullptr; void* p_xg = nullptr;
    cudaGetSymbolAddress(&p_arr, g_arrive_arr);
    cudaGetSymbolAddress(&p_rel, g_release_arr);
    cudaGetSymbolAddress(&p_xg, g_xg);
    cudaMemsetAsync(p_arr, 0, 32 * sizeof(unsigned));
    cudaMemsetAsync(p_rel, 0, 32 * sizeof(unsigned));

    emb_kernel<<<S_LEN, 256>>>(pw, Wemb, bemb);
    xgates_kernel<<<dim3(16, S_LEN), 128, xg_smem>>>(Wih, bih, bhh);
    dummy_kernel<<<1, 1>>>();
    lstm_kernel<<<NCTA, 256, lstm_smem>>>(Whh, h0, c0, (const float*)p_xg);
    readout_kernel<<<S_LEN, 256>>>(Wout, bout, y);
}

// round 4
// speedup vs baseline: 1.4994x; 1.0244x over previous
#include <cuda_runtime.h>
#include <cuda_bf16.h>
#include <cooperative_groups.h>
#include <cstdint>

namespace cg = cooperative_groups;

#define S_LEN 2048
#define B_N   64
#define W5    50
#define E_N   128
#define H_N   256
#define G_N   1024

typedef unsigned long long ull;

// ---------------- static device scratch (allocation-free) ----------------
__device__ float g_emb[(size_t)S_LEN * B_N * E_N];      // [s][b][e]
__device__ float g_xg [(size_t)S_LEN * B_N * G_N];      // [s][b][g]
__device__ float g_hs [(size_t)S_LEN * 16 * H_N * 4];   // [s][cl][j][b4]

__device__ __forceinline__ float sigf(float x) { return 1.0f / (1.0f + __expf(-x)); }
__device__ __forceinline__ float tanhf_fast(float x) {
    float e = __expf(2.0f * x);
    return 1.0f - 2.0f / (e + 1.0f);   // safe at +/-inf
}

__device__ __forceinline__ ull pack2(float lo, float hi) {
    ull r; asm("mov.b64 %0, {%1, %2};" : "=l"(r) : "f"(lo), "f"(hi)); return r;
}
__device__ __forceinline__ void unpack2(ull v, float& lo, float& hi) {
    asm("mov.b64 {%0, %1}, %2;" : "=f"(lo), "=f"(hi) : "l"(v));
}
__device__ __forceinline__ void fma2(ull& d, ull a, ull b) {
    asm("fma.rn.f32x2 %0, %1, %2, %0;" : "+l"(d) : "l"(a), "l"(b));
}
__device__ __forceinline__ ull add2(ull a, ull b) {
    ull r; asm("add.rn.f32x2 %0, %1, %2;" : "=l"(r) : "l"(a), "l"(b)); return r;
}

// =============== Phase 1a: emb = relu(pw @ Wemb^T + bemb) ===============
__global__ void __launch_bounds__(256) emb_kernel(const float* __restrict__ pw,
                                                  const float* __restrict__ Wemb,
                                                  const float* __restrict__ bemb) {
    __shared__ float pw_s[64 * 51];
    __shared__ float we_s[128 * 51];
    const int s = blockIdx.x;
    const int t = threadIdx.x;

    for (int i = t; i < 64 * 50; i += 256) {
        int b = i / 50, k = i - b * 50;
        pw_s[b * 51 + k] = pw[((size_t)b * S_LEN + s) * W5 + k];
    }
    for (int i = t; i < 128 * 50; i += 256) {
        int e = i / 50, k = i - e * 50;
        we_s[e * 51 + k] = Wemb[e * 50 + k];
    }
    __syncthreads();

    const int e = t & 127, bh = t >> 7;
    float wreg[50];
#pragma unroll
    for (int k = 0; k < 50; k++) wreg[k] = we_s[e * 51 + k];
    const float be = bemb[e];
    float* outp = g_emb + (size_t)s * (B_N * E_N);
    for (int bb = 0; bb < 32; bb++) {
        int b = bh * 32 + bb;
        float acc = be;
#pragma unroll
        for (int k = 0; k < 50; k++) acc = fmaf(pw_s[b * 51 + k], wreg[k], acc);
        outp[b * 128 + e] = fmaxf(acc, 0.0f);
    }
}

// =============== Phase 1b: x_gates[s][b][g] = Wih @ emb^T + (bih+bhh) ===============
#define XP 68
#define TPCH 69
__global__ void __launch_bounds__(128) xgates_kernel(const float* __restrict__ Wih,
                                                     const float* __restrict__ bih,
                                                     const float* __restrict__ bhh) {
    extern __shared__ float sm[];
    float* wT = sm;                 // [e=128][g=64] pitch XP
    float* eT = sm + 128 * XP;      // [e=128][b=64] pitch XP
    float* tr = eT + 128 * XP;      // [b=64][g=64]  pitch TPCH
    const int s = blockIdx.y, gt = blockIdx.x;
    const int t = threadIdx.x;

    for (int i = t; i < 64 * 128; i += 128) {
        int e = i & 127, g = i >> 7;
        wT[e * XP + g] = Wih[((size_t)(gt * 64 + g)) * 128 + e];
    }
    const float* embp = g_emb + (size_t)s * (B_N * E_N);
    for (int i = t; i < 64 * 128; i += 128) {
        int e = i & 127, b = i >> 7;
        eT[e * XP + b] = embp[b * 128 + e];
    }
    __syncthreads();

    const int gq = t >> 4;   // 0..7 -> 8 g's
    const int bq = t & 15;   // 4 b's
    float acc[8][4];
#pragma unroll
    for (int i = 0; i < 8; i++)
#pragma unroll
        for (int j = 0; j < 4; j++) acc[i][j] = 0.0f;

#pragma unroll 4
    for (int e = 0; e < 128; e++) {
        float4 w0 = *(float4*)&wT[e * XP + gq * 8];
        float4 w1 = *(float4*)&wT[e * XP + gq * 8 + 4];
        float4 hv = *(float4*)&eT[e * XP + bq * 4];
        float w[8] = {w0.x, w0.y, w0.z, w0.w, w1.x, w1.y, w1.z, w1.w};
        float x[4] = {hv.x, hv.y, hv.z, hv.w};
#pragma unroll
        for (int i = 0; i < 8; i++)
#pragma unroll
            for (int j = 0; j < 4; j++) acc[i][j] = fmaf(w[i], x[j], acc[i][j]);
    }

#pragma unroll
    for (int i = 0; i < 8; i++) {
        int gl = gq * 8 + i;
        int gg = gt * 64 + gl;
        float bs = bih[gg] + bhh[gg];
#pragma unroll
        for (int j = 0; j < 4; j++) tr[(bq * 4 + j) * TPCH + gl] = acc[i][j] + bs;
    }
    __syncthreads();

    float* xgp = g_xg + (size_t)s * (B_N * G_N);
    for (int idx = t; idx < 64 * 64; idx += 128) {
        int b = idx >> 6, g = idx & 63;
        xgp[(size_t)b * G_N + gt * 64 + g] = tr[b * TPCH + g];
    }
}

// =============== Phase 2: clustered LSTM scan (no grid barrier) ===============
// 16 clusters x 8 CTAs x 256 threads. Cluster cl owns batches 4cl..4cl+3.
// CTA rank owns hidden cols j = 32*rank .. +31. Thread: rg = j-local, kq = k-split.
__global__ void __launch_bounds__(256, 1) __cluster_dims__(8, 1, 1)
lstm_kernel(const float* __restrict__ Whh,
            const float* __restrict__ h0,
            const float* __restrict__ c0) {
    __shared__ float4 h_s[2][256];          // [buf][k] x 4 batches

    cg::cluster_group cluster = cg::this_cluster();
    const int rank = (int)cluster.block_rank();
    const int cl   = (int)(blockIdx.x >> 3);
    const int t    = threadIdx.x;
    const int kq   = t & 7;
    const int rg   = t >> 3;                // 0..31
    const int jg   = rank * 32 + rg;        // global hidden index

    // W_hh register-resident pairs: (Wi,Wf) and (Wg,Wo) for column jg, k = 8*kk+kq
    ull wif[32], wgo[32];
#pragma unroll
    for (int kk = 0; kk < 32; kk++) {
        int k = (kk << 3) | kq;
        wif[kk] = pack2(Whh[(size_t)(0 * 256 + jg) * 256 + k],
                        Whh[(size_t)(1 * 256 + jg) * 256 + k]);
        wgo[kk] = pack2(Whh[(size_t)(2 * 256 + jg) * 256 + k],
                        Whh[(size_t)(3 * 256 + jg) * 256 + k]);
    }

    // DSMEM peer pointers (includes self)
    float4* peer[8];
#pragma unroll
    for (int p = 0; p < 8; p++) peer[p] = cluster.map_shared_rank(&h_s[0][0], p);

    // init h buffer 0 from h0 ([b][j] layout)
    {
        float v0 = h0[(4 * cl + 0) * 256 + t];
        float v1 = h0[(4 * cl + 1) * 256 + t];
        float v2 = h0[(4 * cl + 2) * 256 + t];
        float v3 = h0[(4 * cl + 3) * 256 + t];
        h_s[0][t] = make_float4(v0, v1, v2, v3);
    }
    float c = 0.0f;
    if (kq < 4) c = c0[(4 * cl + kq) * 256 + jg];

    // prefetch x-gates for s=0
    float xgi = 0.f, xgf = 0.f, xgg = 0.f, xgo = 0.f;
    if (kq < 4) {
        const float* xp = g_xg + ((size_t)0 * B_N + (4 * cl + kq)) * G_N;
        xgi = xp[0 * 256 + jg]; xgf = xp[1 * 256 + jg];
        xgg = xp[2 * 256 + jg]; xgo = xp[3 * 256 + jg];
    }
    __syncthreads();

    const int lane = t & 31;
    const int obase = lane & 24;            // octet base for gather shfl

    for (int s = 0; s < S_LEN; s++) {
        const float4* hb = h_s[s & 1];
        ull aif0 = 0, aif1 = 0, aif2 = 0, aif3 = 0;
        ull ago0 = 0, ago1 = 0, ago2 = 0, ago3 = 0;
#pragma unroll
        for (int kk = 0; kk < 32; kk++) {
            float4 hv = hb[(kk << 3) | kq];
            ull b0 = pack2(hv.x, hv.x), b1 = pack2(hv.y, hv.y);
            ull b2 = pack2(hv.z, hv.z), b3 = pack2(hv.w, hv.w);
            fma2(aif0, wif[kk], b0); fma2(ago0, wgo[kk], b0);
            fma2(aif1, wif[kk], b1); fma2(ago1, wgo[kk], b1);
            fma2(aif2, wif[kk], b2); fma2(ago2, wgo[kk], b2);
            fma2(aif3, wif[kk], b3); fma2(ago3, wgo[kk], b3);
        }

        // butterfly reduce over the 8 kq lanes
#pragma unroll
        for (int off = 1; off < 8; off <<= 1) {
            aif0 = add2(aif0, __shfl_xor_sync(0xffffffffu, aif0, off));
            aif1 = add2(aif1, __shfl_xor_sync(0xffffffffu, aif1, off));
            aif2 = add2(aif2, __shfl_xor_sync(0xffffffffu, aif2, off));
            aif3 = add2(aif3, __shfl_xor_sync(0xffffffffu, aif3, off));
            ago0 = add2(ago0, __shfl_xor_sync(0xffffffffu, ago0, off));
            ago1 = add2(ago1, __shfl_xor_sync(0xffffffffu, ago1, off));
            ago2 = add2(ago2, __shfl_xor_sync(0xffffffffu, ago2, off));
            ago3 = add2(ago3, __shfl_xor_sync(0xffffffffu, ago3, off));
        }

        // lanes kq=0..3 update batch b=kq for column jg
        float hval = 0.0f;
        if (kq < 4) {
            ull aif = (kq == 0) ? aif0 : (kq == 1) ? aif1 : (kq == 2) ? aif2 : aif3;
            ull ago = (kq == 0) ? ago0 : (kq == 1) ? ago1 : (kq == 2) ? ago2 : ago3;
            float si, sf, sg, so;
            unpack2(aif, si, sf);
            unpack2(ago, sg, so);
            float iv = sigf(si + xgi);
            float fv = sigf(sf + xgf);
            float gv = tanhf_fast(sg + xgg);
            float ov = sigf(so + xgo);
            c = fv * c + iv * gv;
            hval = ov * tanhf_fast(c);
        }

        // gather 4 batch-values into kq==0 lane, broadcast h to all 8 CTAs
        float hx = __shfl_sync(0xffffffffu, hval, obase + 0);
        float hy = __shfl_sync(0xffffffffu, hval, obase + 1);
        float hz = __shfl_sync(0xffffffffu, hval, obase + 2);
        float hw = __shfl_sync(0xffffffffu, hval, obase + 3);
        if (kq == 0) {
            float4 o4 = make_float4(hx, hy, hz, hw);
            int slot = (((s + 1) & 1) << 8) + jg;
#pragma unroll
            for (int p = 0; p < 8; p++) peer[p][slot] = o4;
            *(float4*)&g_hs[(((size_t)s * 16 + cl) * 256 + jg) * 4] = o4;
        }

        asm volatile("barrier.cluster.arrive.aligned;" ::: "memory");

        // prefetch next step's x-gates while waiting
        if (kq < 4 && s + 1 < S_LEN) {
            const float* xp = g_xg + ((size_t)(s + 1) * B_N + (4 * cl + kq)) * G_N;
            xgi = xp[0 * 256 + jg]; xgf = xp[1 * 256 + jg];
            xgg = xp[2 * 256 + jg]; xgo = xp[3 * 256 + jg];
        }

        asm volatile("barrier.cluster.wait.aligned;" ::: "memory");
    }
}

// dummy kernel so ncu -s 5 -c 1 lands on lstm_kernel
__global__ void dummy_kernel() {}

// =============== Phase 3: readout, g_hs is [s][cl][j][b4] ===============
__global__ void __launch_bounds__(256) readout_kernel(const float* __restrict__ Wout,
                                                      const float* __restrict__ bout,
                                                      float* __restrict__ y) {
    __shared__ float part[4][64];
    const int s = blockIdx.x;
    const int t = threadIdx.x;
    const int p = t & 63;          // p == global batch (cl = p>>2, bq = p&3)
    const int q = t >> 6;          // j-quarter
    const float* hp = g_hs + (((size_t)s * 16 + (p >> 2)) * 256) * 4 + (p & 3);
    float acc = 0.0f;
#pragma unroll 8
    for (int j = q * 64; j < q * 64 + 64; j++)
        acc = fmaf(hp[(size_t)j * 4], Wout[j], acc);
    part[q][p] = acc;
    __syncthreads();
    if (t < 64) {
        float v = part[0][t] + part[1][t] + part[2][t] + part[3][t] + bout[0];
        y[s * 64 + t] = sigf(v);
    }
}

// =============== host launcher ===============
extern "C" void kernel_launch(void* const* d_in, const int* in_sizes, int n_in,
                              void* d_out, int out_size) {
    const float* pw   = (const float*)d_in[0];
    const float* Wemb = (const float*)d_in[1];
    const float* bemb = (const float*)d_in[2];
    const float* Wih  = (const float*)d_in[3];
    const float* Whh  = (const float*)d_in[4];
    const float* bih  = (const float*)d_in[5];
    const float* bhh  = (const float*)d_in[6];
    const float* Wout = (const float*)d_in[7];
    const float* bout = (const float*)d_in[8];
    const float* h0   = (const float*)d_in[9];
    const float* c0   = (const float*)d_in[10];
    float* y = (float*)d_out;

    static bool attrs_set = false;
    const int xg_smem = (2 * 128 * XP + 64 * TPCH) * (int)sizeof(float);
    if (!attrs_set) {
        cudaFuncSetAttribute(xgates_kernel, cudaFuncAttributeMaxDynamicSharedMemorySize, xg_smem);
        attrs_set = true;
    }

    emb_kernel<<<S_LEN, 256>>>(pw, Wemb, bemb);
    xgates_kernel<<<dim3(16, S_LEN), 128, xg_smem>>>(Wih, bih, bhh);
    dummy_kernel<<<1, 1>>>();
    lstm_kernel<<<128, 256>>>(Whh, h0, c0);
    readout_kernel<<<S_LEN, 256>>>(Wout, bout, y);
}